// round 17
// baseline (speedup 1.0000x reference)
#include <cuda_runtime.h>
#include <cuda_bf16.h>
#include <cstdint>

#define NLEV 4
#define MAXS 792
#define NTHREADS 256
#define NBLOCKS 444   // 148 SMs x 3 blocks/SM

// Packed table: level sizes 36/72/216/792 -> offsets 0/36/108/324, 1116 float2 (8.9KB)
#define T_TOT 1116

// R16: persistent depth-1 register pipeline (R15 winner) with address-path
// micro-tuning: compile-time toff per unrolled level (no LDS on the gather
// chain), 32-bit hoisted row offsets, branchless clamped prefetch index.
__global__ __launch_bounds__(NTHREADS, 3) void heal_encoding_persistpipe2(
    const float2* __restrict__ params2,      // [NLEV, MAXS] float2
    const float2* __restrict__ pixel_ll,     // [NLEV, B]
    const float2* __restrict__ neigh_ll,     // [NLEV, 8, B]
    const int*    __restrict__ pixel_idx,    // [NLEV, B]
    const int*    __restrict__ neigh_idx,    // [NLEV, 8, B]
    float*        __restrict__ out,          // [B, 8]  out[b, 4f+l]
    int B)
{
    __shared__ float2 tab[T_TOT];

    const int gtid    = blockIdx.x * NTHREADS + threadIdx.x;
    const int gstride = gridDim.x * NTHREADS;

    // double-buffered per-level inputs (registers, statically indexed)
    int    nidx[2][8];
    float2 nll [2][8];
    int    p   [2];
    float2 pl  [2];

    // ---- prologue: issue (sample gtid, level 0) loads BEFORE table copy ----
    {
        const int b0 = (gtid < B) ? gtid : 0;
#pragma unroll
        for (int j = 0; j < 8; j++)
            nidx[0][j] = __ldcs(neigh_idx + j * B + b0);
#pragma unroll
        for (int j = 0; j < 8; j++)
            nll[0][j]  = __ldcs(neigh_ll  + j * B + b0);
        p[0]  = __ldcs(pixel_idx + b0);
        pl[0] = __ldcs(pixel_ll  + b0);
    }

    // ---- table copy + barrier (covers prologue load latency) ----
    {
        const int tsz[NLEV]  = {36, 72, 216, 792};
        const int toff[NLEV] = {0, 36, 108, 324};
#pragma unroll
        for (int l = 0; l < NLEV; l++)
            for (int i = threadIdx.x; i < tsz[l]; i += NTHREADS)
                tab[toff[l] + i] = params2[l * MAXS + i];
    }
    __syncthreads();

    float acc0[NLEV], acc1[NLEV];

    for (int b = gtid; b < B; b += gstride) {
        // branchless clamped next-sample index: if b+gstride >= B, prefetch
        // re-reads the current sample's level-0 row (harmless, discarded).
        const int bn = (b + gstride < B) ? (b + gstride) : b;

#pragma unroll
        for (int l = 0; l < NLEV; l++) {
            const int cur = l & 1;                // 4 items/sample -> parity stable
            const int nxt = cur ^ 1;

            // prefetch next item: (b, l+1) or (bn, 0). All row offsets are
            // compile-time-known multiples of B (32-bit), hoisted by ptxas.
            const int pf_lvl = (l + 1) & 3;       // 1,2,3,0
            const int pf_b   = (l + 1 < NLEV) ? b : bn;
#pragma unroll
            for (int j = 0; j < 8; j++)
                nidx[nxt][j] = __ldcs(neigh_idx + (pf_lvl * 8 + j) * B + pf_b);
#pragma unroll
            for (int j = 0; j < 8; j++)
                nll[nxt][j]  = __ldcs(neigh_ll  + (pf_lvl * 8 + j) * B + pf_b);
            p[nxt]  = __ldcs(pixel_idx + pf_lvl * B + pf_b);
            pl[nxt] = __ldcs(pixel_ll  + pf_lvl * B + pf_b);

            // compute (b, l) from buffer cur; toff is a compile-time constant
            const int    to = (l == 3) ? 324 : ((l == 2) ? 108 : l * 36);
            const float2 P  = pl[cur];
            const float2 r  = tab[to + p[cur]];
            float s0 = r.x, s1 = r.y;
#pragma unroll
            for (int j = 0; j < 8; j++) {
                const int    n  = nidx[cur][j];
                const float2 ll = nll[cur][j];
                const float dphi = ll.y - P.y;
                const float dth  = ll.x - P.x;
                float w = rsqrtf(fmaf(dphi, dphi, dth * dth));
                w = (n >= 0) ? w : 0.0f;
                const float2 v = tab[to + (n >= 0 ? n : 0)];
                s0 = fmaf(w, v.x, s0);
                s1 = fmaf(w, v.y, s1);
            }
            acc0[l] = s0;
            acc1[l] = s1;
        }

        // out[b, 4f + l]: 8 contiguous floats -> two streaming float4 stores
        float4* op = reinterpret_cast<float4*>(out + (size_t)b * 8);
        __stcs(op,     make_float4(acc0[0], acc0[1], acc0[2], acc0[3]));
        __stcs(op + 1, make_float4(acc1[0], acc1[1], acc1[2], acc1[3]));
    }
}

extern "C" void kernel_launch(void* const* d_in, const int* in_sizes, int n_in,
                              void* d_out, int out_size)
{
    // metadata order: params, pixel_latlon, neigh_latlon, pixel_index, neigh_index
    const float2* params2   = (const float2*)d_in[0];
    const float2* pixel_ll  = (const float2*)d_in[1];
    const float2* neigh_ll  = (const float2*)d_in[2];
    const int*    pixel_idx = (const int*)d_in[3];
    const int*    neigh_idx = (const int*)d_in[4];
    float*        out       = (float*)d_out;

    const int B = in_sizes[3] / NLEV;   // pixel_index has NLEV*B elements

    heal_encoding_persistpipe2<<<NBLOCKS, NTHREADS>>>(
        params2, pixel_ll, neigh_ll, pixel_idx, neigh_idx, out, B);
}